// round 3
// baseline (speedup 1.0000x reference)
#include <cuda_runtime.h>

#define N_NODES 100000
#define N_GRAPHS 100
#define NPG 1000
#define NEDGE 1600000
#define HID 128
#define RD 64
#define SLOPE 0.01f

// ----------------------------------------------------------------------------
// Scratch (device globals — no allocations allowed)
// ----------------------------------------------------------------------------
__device__ __align__(16) float g_bufA[N_NODES * HID];   // X@W products / phi
__device__ __align__(16) float g_bufB[N_NODES * HID];   // aggregated (pre-norm)
__device__ __align__(16) float g_hbuf[N_NODES * HID];   // layer output h
__device__ int   g_deg_out[N_NODES];
__device__ int   g_deg_in[N_NODES];
__device__ float g_iso[N_NODES];
__device__ float g_isi[N_NODES];
__device__ int   g_offs[N_NODES + 1];
__device__ int   g_cursor[N_NODES];
__device__ int   g_csr_src[NEDGE];
__device__ float g_csr_w[NEDGE];
__device__ __align__(16) float g_pool[N_GRAPHS * HID];
__device__ __align__(16) float g_m1[N_GRAPHS * HID];
__device__ __align__(16) float g_m2[N_GRAPHS * HID];
__device__ __align__(16) float g_r1[N_GRAPHS * RD];
__device__ __align__(16) float g_r2[N_GRAPHS * RD];

__device__ __forceinline__ float leaky(float v) { return v >= 0.0f ? v : SLOPE * v; }

// ----------------------------------------------------------------------------
// Prep kernels: degrees, scan, CSR build
// ----------------------------------------------------------------------------
__global__ void zero_kernel() {
    int i = blockIdx.x * blockDim.x + threadIdx.x;
    if (i < N_NODES) { g_deg_out[i] = 0; g_deg_in[i] = 0; }
}

__global__ void degree_kernel(const int* __restrict__ src, const int* __restrict__ dst) {
    int e = blockIdx.x * blockDim.x + threadIdx.x;
    if (e >= NEDGE) return;
    atomicAdd(&g_deg_out[src[e]], 1);
    atomicAdd(&g_deg_in[dst[e]], 1);
}

__global__ void isqrt_kernel() {
    int i = blockIdx.x * blockDim.x + threadIdx.x;
    if (i >= N_NODES) return;
    int dо = g_deg_out[i]; if (dо < 1) dо = 1;
    int di = g_deg_in[i];  if (di < 1) di = 1;
    g_iso[i] = rsqrtf((float)dо);
    g_isi[i] = rsqrtf((float)di);
}

// single-block exclusive scan of deg_in -> offs, cursor
__global__ void scan_kernel() {
    __shared__ int sm[1024];
    const int t = threadIdx.x;
    const int CH = (N_NODES + 1023) / 1024;  // 98
    int beg = t * CH;
    int end = beg + CH; if (end > N_NODES) end = N_NODES;
    int s = 0;
    for (int i = beg; i < end && i < N_NODES; i++) s += g_deg_in[i];
    sm[t] = s;
    __syncthreads();
    for (int off = 1; off < 1024; off <<= 1) {
        int add = 0;
        if (t >= off) add = sm[t - off];
        __syncthreads();
        if (t >= off) sm[t] += add;
        __syncthreads();
    }
    int run = (t == 0) ? 0 : sm[t - 1];
    for (int i = beg; i < end && i < N_NODES; i++) {
        g_offs[i] = run;
        g_cursor[i] = run;
        run += g_deg_in[i];
    }
    if (t == 1023) g_offs[N_NODES] = sm[1023];
}

__global__ void csr_kernel(const int* __restrict__ src, const int* __restrict__ dst,
                           const float* __restrict__ ew) {
    int e = blockIdx.x * blockDim.x + threadIdx.x;
    if (e >= NEDGE) return;
    int d = dst[e];
    int p = atomicAdd(&g_cursor[d], 1);
    g_csr_src[p] = src[e];
    g_csr_w[p] = ew[e];
}

// ----------------------------------------------------------------------------
// GEMM: Y[N,128] = act( (SCALE? X*iso : X) @ W + bias ), fp32 via packed f32x2
// block = 128 threads (one output column each), 32 rows per block
// ----------------------------------------------------------------------------
template <int K, bool ACT, bool SCALE>
__global__ __launch_bounds__(128) void gemm_kernel(
    const float* __restrict__ X, const float* __restrict__ W,
    const float* __restrict__ bias, float* __restrict__ Y)
{
    constexpr int RB = 32;
    __shared__ __align__(16) float xs[RB / 2][K / 2][4];  // [rowpair][k/2][(k&1)*2 + rowparity]
    const int c = threadIdx.x;
    const int row0 = blockIdx.x * RB;

    // load X tile (scaled), repacked into row-pair / k-pair quads
    for (int idx = threadIdx.x; idx < RB * K / 4; idx += 128) {
        int r = idx / (K / 4);
        int k4 = idx - r * (K / 4);
        float4 v = reinterpret_cast<const float4*>(X + (size_t)(row0 + r) * K)[k4];
        float s = SCALE ? g_iso[row0 + r] : 1.0f;
        int rp = r >> 1, rb = r & 1;
        float vv[4] = {v.x, v.y, v.z, v.w};
#pragma unroll
        for (int i = 0; i < 4; i++) {
            int k = k4 * 4 + i;
            xs[rp][k >> 1][((k & 1) << 1) | rb] = vv[i] * s;
        }
    }
    __syncthreads();

    unsigned long long acc[16];
#pragma unroll
    for (int i = 0; i < 16; i++) acc[i] = 0ULL;

#pragma unroll 1
    for (int c0 = 0; c0 < K; c0 += 16) {
        unsigned long long wp[16];
#pragma unroll
        for (int i = 0; i < 16; i++) {
            float w = W[(c0 + i) * HID + c];
            asm("mov.b64 %0, {%1, %1};" : "=l"(wp[i]) : "f"(w));
        }
#pragma unroll
        for (int rp = 0; rp < 16; rp++) {
            const float4* xp = reinterpret_cast<const float4*>(&xs[rp][c0 >> 1][0]);
#pragma unroll
            for (int i = 0; i < 8; i++) {
                float4 v = xp[i];  // (r0@k, r1@k, r0@k+1, r1@k+1), broadcast LDS.128
                unsigned long long p0, p1;
                asm("mov.b64 %0, {%1, %2};" : "=l"(p0) : "f"(v.x), "f"(v.y));
                asm("mov.b64 %0, {%1, %2};" : "=l"(p1) : "f"(v.z), "f"(v.w));
                asm("fma.rn.f32x2 %0, %1, %2, %0;" : "+l"(acc[rp]) : "l"(p0), "l"(wp[2 * i]));
                asm("fma.rn.f32x2 %0, %1, %2, %0;" : "+l"(acc[rp]) : "l"(p1), "l"(wp[2 * i + 1]));
            }
        }
    }

    float b = bias ? bias[c] : 0.0f;
#pragma unroll
    for (int rp = 0; rp < 16; rp++) {
        float lo, hi;
        asm("mov.b64 {%0, %1}, %2;" : "=f"(lo), "=f"(hi) : "l"(acc[rp]));
        lo += b; hi += b;
        if (ACT) { lo = leaky(lo); hi = leaky(hi); }
        Y[(size_t)(row0 + 2 * rp + 0) * HID + c] = lo;
        Y[(size_t)(row0 + 2 * rp + 1) * HID + c] = hi;
    }
}

// ----------------------------------------------------------------------------
// Gather: g_bufB[n] = isi[n] * sum_{e in-edges(n)} g_bufA[src_e] * w_e
// warp per node, lane = float4 channel chunk
// ----------------------------------------------------------------------------
__global__ __launch_bounds__(128) void gather_kernel() {
    int n = blockIdx.x * 4 + (threadIdx.x >> 5);
    int lane = threadIdx.x & 31;
    if (n >= N_NODES) return;
    int beg = g_offs[n], end = g_offs[n + 1];
    const float4* msg = reinterpret_cast<const float4*>(g_bufA);
    float4 a0 = {0, 0, 0, 0}, a1 = {0, 0, 0, 0};
    int j = beg;
    for (; j + 2 <= end; j += 2) {
        int s0 = g_csr_src[j], s1 = g_csr_src[j + 1];
        float w0 = g_csr_w[j], w1 = g_csr_w[j + 1];
        float4 v0 = msg[s0 * 32 + lane];
        float4 v1 = msg[s1 * 32 + lane];
        a0.x += v0.x * w0; a0.y += v0.y * w0; a0.z += v0.z * w0; a0.w += v0.w * w0;
        a1.x += v1.x * w1; a1.y += v1.y * w1; a1.z += v1.z * w1; a1.w += v1.w * w1;
    }
    if (j < end) {
        int s0 = g_csr_src[j]; float w0 = g_csr_w[j];
        float4 v0 = msg[s0 * 32 + lane];
        a0.x += v0.x * w0; a0.y += v0.y * w0; a0.z += v0.z * w0; a0.w += v0.w * w0;
    }
    float si = g_isi[n];
    float4 r;
    r.x = (a0.x + a1.x) * si; r.y = (a0.y + a1.y) * si;
    r.z = (a0.z + a1.z) * si; r.w = (a0.w + a1.w) * si;
    reinterpret_cast<float4*>(g_bufB)[n * 32 + lane] = r;
}

// ----------------------------------------------------------------------------
// GraphNorm + leaky + mean pool. x = g_bufB, y = g_hbuf, mout = m1/m2
// block per graph, 512 threads = 4 node-groups x 128 channels
// ----------------------------------------------------------------------------
__global__ __launch_bounds__(512) void norm_kernel(
    const float* __restrict__ alpha, const float* __restrict__ gamma,
    const float* __restrict__ beta, float* __restrict__ mout)
{
    __shared__ float s1[4][HID], s2[4][HID];
    __shared__ float s_ma[HID], s_sc[HID], s_bt[HID];
    const int c = threadIdx.x & 127;
    const int q = threadIdx.x >> 7;
    const int g = blockIdx.x;
    const int nbeg = g * NPG + q * (NPG / 4);
    float s = 0.0f, ss = 0.0f;
#pragma unroll 4
    for (int i = 0; i < NPG / 4; i++) {
        float v = g_bufB[(size_t)(nbeg + i) * HID + c];
        s += v; ss += v * v;
    }
    s1[q][c] = s; s2[q][c] = ss;
    __syncthreads();
    if (q == 0) {
        float S  = s1[0][c] + s1[1][c] + s1[2][c] + s1[3][c];
        float SS = s2[0][c] + s2[1][c] + s2[2][c] + s2[3][c];
        float mean = S * (1.0f / NPG);
        float a = alpha[c];
        // E[(x - a*mean)^2] = E[x^2] - mean^2 * a * (2 - a)
        float var = SS * (1.0f / NPG) - mean * mean * a * (2.0f - a);
        s_ma[c] = a * mean;
        s_sc[c] = gamma[c] * rsqrtf(var + 1e-5f);
        s_bt[c] = beta[c];
    }
    __syncthreads();
    float ma = s_ma[c], sc = s_sc[c], bt = s_bt[c];
    float ms = 0.0f;
#pragma unroll 4
    for (int i = 0; i < NPG / 4; i++) {
        float v = g_bufB[(size_t)(nbeg + i) * HID + c];
        float y = leaky(sc * (v - ma) + bt);
        g_hbuf[(size_t)(nbeg + i) * HID + c] = y;
        ms += y;
    }
    s1[q][c] = ms;
    __syncthreads();
    if (q == 0)
        mout[g * HID + c] = (s1[0][c] + s1[1][c] + s1[2][c] + s1[3][c]) * (1.0f / NPG);
}

// mean-pool phi (g_bufA) over graph -> g_pool
__global__ __launch_bounds__(512) void pool_kernel() {
    __shared__ float s1[4][HID];
    const int c = threadIdx.x & 127;
    const int q = threadIdx.x >> 7;
    const int g = blockIdx.x;
    const int nbeg = g * NPG + q * (NPG / 4);
    float s = 0.0f;
#pragma unroll 4
    for (int i = 0; i < NPG / 4; i++)
        s += g_bufA[(size_t)(nbeg + i) * HID + c];
    s1[q][c] = s;
    __syncthreads();
    if (q == 0)
        g_pool[g * HID + c] = (s1[0][c] + s1[1][c] + s1[2][c] + s1[3][c]) * (1.0f / NPG);
}

// rho: r[g][j] = leaky( pool[g] . w2[:,j] + b2[j] )   (w2: [128,64] row-major)
__global__ __launch_bounds__(64) void rho_kernel(
    const float* __restrict__ w2, const float* __restrict__ b2, float* __restrict__ r)
{
    __shared__ float p[HID];
    const int g = blockIdx.x, j = threadIdx.x;
    for (int k = j; k < HID; k += 64) p[k] = g_pool[g * HID + k];
    __syncthreads();
    float acc = b2[j];
#pragma unroll 8
    for (int k = 0; k < HID; k++) acc += p[k] * w2[k * RD + j];
    r[g * RD + j] = leaky(acc);
}

// final assemble: out = leaky(concat(r1, m1, r2, m2))  -> [100, 384]
__global__ void final_kernel(float* __restrict__ out) {
    int i = blockIdx.x * blockDim.x + threadIdx.x;
    if (i >= N_GRAPHS * 384) return;
    int g = i / 384, k = i - g * 384;
    float v;
    if (k < 64)        v = g_r1[g * RD + k];
    else if (k < 192)  v = g_m1[g * HID + (k - 64)];
    else if (k < 256)  v = g_r2[g * RD + (k - 192)];
    else               v = g_m2[g * HID + (k - 256)];
    out[i] = leaky(v);
}

// ----------------------------------------------------------------------------
// Launch
// ----------------------------------------------------------------------------
extern "C" void kernel_launch(void* const* d_in, const int* in_sizes, int n_in,
                              void* d_out, int out_size)
{
    const float* node_feats = (const float*)d_in[0];
    const float* edge_w     = (const float*)d_in[1];
    const float* W1         = (const float*)d_in[2];
    const float* W2         = (const float*)d_in[3];
    const float* gn1a = (const float*)d_in[4];
    const float* gn1g = (const float*)d_in[5];
    const float* gn1b = (const float*)d_in[6];
    const float* gn2a = (const float*)d_in[7];
    const float* gn2g = (const float*)d_in[8];
    const float* gn2b = (const float*)d_in[9];
    const float* r1w1 = (const float*)d_in[10];
    const float* r1b1 = (const float*)d_in[11];
    const float* r1w2 = (const float*)d_in[12];
    const float* r1b2 = (const float*)d_in[13];
    const float* r2w1 = (const float*)d_in[14];
    const float* r2b1 = (const float*)d_in[15];
    const float* r2w2 = (const float*)d_in[16];
    const float* r2b2 = (const float*)d_in[17];
    const int* src = (const int*)d_in[18];
    const int* dst = (const int*)d_in[19];

    float *pA, *pH, *pM1, *pM2, *pR1, *pR2;
    cudaGetSymbolAddress((void**)&pA,  g_bufA);
    cudaGetSymbolAddress((void**)&pH,  g_hbuf);
    cudaGetSymbolAddress((void**)&pM1, g_m1);
    cudaGetSymbolAddress((void**)&pM2, g_m2);
    cudaGetSymbolAddress((void**)&pR1, g_r1);
    cudaGetSymbolAddress((void**)&pR2, g_r2);

    const int NB = (N_NODES + 255) / 256;
    const int EB = (NEDGE + 255) / 256;

    zero_kernel<<<NB, 256>>>();
    degree_kernel<<<EB, 256>>>(src, dst);
    scan_kernel<<<1, 1024>>>();
    isqrt_kernel<<<NB, 256>>>();
    csr_kernel<<<EB, 256>>>(src, dst, edge_w);

    // ---- layer 1 ----
    gemm_kernel<64, false, true><<<N_NODES / 32, 128>>>(node_feats, W1, nullptr, pA);
    gather_kernel<<<N_NODES / 4, 128>>>();
    norm_kernel<<<N_GRAPHS, 512>>>(gn1a, gn1g, gn1b, pM1);
    gemm_kernel<128, true, false><<<N_NODES / 32, 128>>>(pH, r1w1, r1b1, pA);
    pool_kernel<<<N_GRAPHS, 512>>>();
    rho_kernel<<<N_GRAPHS, 64>>>(r1w2, r1b2, pR1);

    // ---- layer 2 ----
    gemm_kernel<128, false, true><<<N_NODES / 32, 128>>>(pH, W2, nullptr, pA);
    gather_kernel<<<N_NODES / 4, 128>>>();
    norm_kernel<<<N_GRAPHS, 512>>>(gn2a, gn2g, gn2b, pM2);
    gemm_kernel<128, true, false><<<N_NODES / 32, 128>>>(pH, r2w1, r2b1, pA);
    pool_kernel<<<N_GRAPHS, 512>>>();
    rho_kernel<<<N_GRAPHS, 64>>>(r2w2, r2b2, pR2);

    final_kernel<<<(N_GRAPHS * 384 + 255) / 256, 256>>>((float*)d_out);
}

// round 4
// speedup vs baseline: 1.4627x; 1.4627x over previous
#include <cuda_runtime.h>

#define N_NODES 100000
#define N_GRAPHS 100
#define NPG 1000
#define NEDGE 1600000
#define EPG (NEDGE / N_GRAPHS)   // 16000 edges per graph (contiguous)
#define HID 128
#define RD 64
#define SLOPE 0.01f

// ----------------------------------------------------------------------------
// Scratch (device globals — no allocations allowed)
// ----------------------------------------------------------------------------
__device__ __align__(16) float g_agg[N_NODES * HID];    // gather output (64 or 128 wide)
__device__ __align__(16) float g_conv[N_NODES * HID];   // GEMM output, pre-norm
__device__ __align__(16) float g_h1[N_NODES * HID];     // layer-1 output
__device__ __align__(16) float g_h2[N_NODES * HID];     // layer-2 output
__device__ __align__(16) float g_phi[N_NODES * HID];    // readout phi output
__device__ float g_isi[N_NODES];
__device__ int   g_offs[N_NODES + 1];
__device__ int   g_csr_src[NEDGE];
__device__ float g_csr_w[NEDGE];                        // ew * iso[src] pre-folded
__device__ __align__(16) float g_pool[N_GRAPHS * HID];
__device__ __align__(16) float g_m1[N_GRAPHS * HID];
__device__ __align__(16) float g_m2[N_GRAPHS * HID];
__device__ __align__(16) float g_r1[N_GRAPHS * RD];
__device__ __align__(16) float g_r2[N_GRAPHS * RD];

__device__ __forceinline__ float leaky(float v) { return v >= 0.0f ? v : SLOPE * v; }

// ----------------------------------------------------------------------------
// Prep: per-graph degree histograms, iso/isi, shared scan, CSR build.
// One block per graph, 512 threads, shared atomics only.
// ----------------------------------------------------------------------------
__global__ __launch_bounds__(512) void prep_kernel(const int* __restrict__ src,
                                                   const int* __restrict__ dst,
                                                   const float* __restrict__ ew)
{
    __shared__ int   sdin[NPG], sdout[NPG], scur[NPG];
    __shared__ float siso[NPG];
    __shared__ int   ssum[512];
    const int g = blockIdx.x, t = threadIdx.x;
    const int ebeg = g * EPG, eend = ebeg + EPG;
    const int nbase = g * NPG;

    for (int i = t; i < NPG; i += 512) { sdin[i] = 0; sdout[i] = 0; }
    __syncthreads();
    for (int e = ebeg + t; e < eend; e += 512) {
        atomicAdd(&sdout[src[e] - nbase], 1);
        atomicAdd(&sdin[dst[e] - nbase], 1);
    }
    __syncthreads();
    for (int i = t; i < NPG; i += 512) {
        int dq = sdout[i]; if (dq < 1) dq = 1;
        int di = sdin[i];  if (di < 1) di = 1;
        siso[i] = rsqrtf((float)dq);
        g_isi[nbase + i] = rsqrtf((float)di);
    }
    __syncthreads();
    // exclusive scan of sdin (1000 elems): thread t owns 2t, 2t+1
    int a0 = (2 * t < NPG) ? sdin[2 * t] : 0;
    int a1 = (2 * t + 1 < NPG) ? sdin[2 * t + 1] : 0;
    ssum[t] = a0 + a1;
    __syncthreads();
    for (int off = 1; off < 512; off <<= 1) {
        int v = (t >= off) ? ssum[t - off] : 0;
        __syncthreads();
        ssum[t] += v;
        __syncthreads();
    }
    int excl = (t == 0) ? 0 : ssum[t - 1];
    if (2 * t < NPG)     { scur[2 * t]     = excl;      g_offs[nbase + 2 * t]     = ebeg + excl; }
    if (2 * t + 1 < NPG) { scur[2 * t + 1] = excl + a0; g_offs[nbase + 2 * t + 1] = ebeg + excl + a0; }
    if (g == N_GRAPHS - 1 && t == 0) g_offs[N_NODES] = NEDGE;
    __syncthreads();
    // CSR placement with iso folded into the edge weight
    for (int e = ebeg + t; e < eend; e += 512) {
        int sl = src[e] - nbase, dl = dst[e] - nbase;
        int p = atomicAdd(&scur[dl], 1);
        g_csr_src[ebeg + p] = src[e];
        g_csr_w[ebeg + p]   = ew[e] * siso[sl];
    }
}

// ----------------------------------------------------------------------------
// Gather: OUT[n] = isi[n] * sum_{in-edges} X[src] * w.  Warp per node.
// F = feature width (64 -> float2/lane, 128 -> float4/lane). MLP=8 batches.
// ----------------------------------------------------------------------------
template <int F>
__global__ __launch_bounds__(256) void gather_kernel(const float* __restrict__ X,
                                                     float* __restrict__ OUT)
{
    const int n = blockIdx.x * 8 + (threadIdx.x >> 5);
    const int lane = threadIdx.x & 31;
    const int beg = g_offs[n], end = g_offs[n + 1];
    const float si = g_isi[n];

    if (F == 128) {
        const float4* Xv = reinterpret_cast<const float4*>(X);
        float ax = 0, ay = 0, az = 0, aw = 0;
        int j = beg;
        for (; j + 8 <= end; j += 8) {
            int s[8]; float w[8];
#pragma unroll
            for (int q = 0; q < 8; q++) { s[q] = g_csr_src[j + q]; w[q] = g_csr_w[j + q]; }
#pragma unroll
            for (int q = 0; q < 8; q++) {
                float4 v = Xv[(size_t)s[q] * 32 + lane];
                ax += v.x * w[q]; ay += v.y * w[q]; az += v.z * w[q]; aw += v.w * w[q];
            }
        }
        for (; j < end; j++) {
            int s0 = g_csr_src[j]; float w0 = g_csr_w[j];
            float4 v = Xv[(size_t)s0 * 32 + lane];
            ax += v.x * w0; ay += v.y * w0; az += v.z * w0; aw += v.w * w0;
        }
        float4 r; r.x = ax * si; r.y = ay * si; r.z = az * si; r.w = aw * si;
        reinterpret_cast<float4*>(OUT)[(size_t)n * 32 + lane] = r;
    } else {  // F == 64
        const float2* Xv = reinterpret_cast<const float2*>(X);
        float ax = 0, ay = 0;
        int j = beg;
        for (; j + 8 <= end; j += 8) {
            int s[8]; float w[8];
#pragma unroll
            for (int q = 0; q < 8; q++) { s[q] = g_csr_src[j + q]; w[q] = g_csr_w[j + q]; }
#pragma unroll
            for (int q = 0; q < 8; q++) {
                float2 v = Xv[(size_t)s[q] * 32 + lane];
                ax += v.x * w[q]; ay += v.y * w[q];
            }
        }
        for (; j < end; j++) {
            int s0 = g_csr_src[j]; float w0 = g_csr_w[j];
            float2 v = Xv[(size_t)s0 * 32 + lane];
            ax += v.x * w0; ay += v.y * w0;
        }
        float2 r; r.x = ax * si; r.y = ay * si;
        reinterpret_cast<float2*>(OUT)[(size_t)n * 32 + lane] = r;
    }
}

// ----------------------------------------------------------------------------
// GEMM: Y[N,128] = act( X @ W + bias ), fp32 via packed fma.rn.f32x2.
// 128 threads (one output column each), 32 rows/block. Shared tile stores
// row-pair/k-pair quads so a single LDS.128 yields two ready packed operands.
// ----------------------------------------------------------------------------
template <int K, bool ACT>
__global__ __launch_bounds__(128) void gemm_kernel(const float* __restrict__ X,
                                                   const float* __restrict__ W,
                                                   const float* __restrict__ bias,
                                                   float* __restrict__ Y)
{
    constexpr int RB = 32;
    __shared__ __align__(16) float xs[RB / 2][K / 2][4];  // [rowpair][k/2][2*(k&1)+rowparity]
    const int c = threadIdx.x;
    const int row0 = blockIdx.x * RB;

    for (int idx = threadIdx.x; idx < RB * K / 4; idx += 128) {
        int r = idx / (K / 4);
        int k4 = idx - r * (K / 4);
        float4 v = reinterpret_cast<const float4*>(X + (size_t)(row0 + r) * K)[k4];
        int rp = r >> 1, rb = r & 1;
        float vv[4] = {v.x, v.y, v.z, v.w};
#pragma unroll
        for (int i = 0; i < 4; i++) {
            int k = k4 * 4 + i;
            xs[rp][k >> 1][((k & 1) << 1) | rb] = vv[i];
        }
    }
    __syncthreads();

    unsigned long long acc[16];
#pragma unroll
    for (int i = 0; i < 16; i++) acc[i] = 0ULL;

#pragma unroll 1
    for (int c0 = 0; c0 < K; c0 += 16) {
        unsigned long long wp[16];
#pragma unroll
        for (int i = 0; i < 16; i++) {
            float w = W[(c0 + i) * HID + c];
            asm("mov.b64 %0, {%1, %1};" : "=l"(wp[i]) : "f"(w));
        }
#pragma unroll
        for (int rp = 0; rp < 16; rp++) {
            const ulonglong2* xq = reinterpret_cast<const ulonglong2*>(&xs[rp][c0 >> 1][0]);
#pragma unroll
            for (int i = 0; i < 4; i++) {
                ulonglong2 qa = xq[2 * i];       // k-pair (c0+4i, c0+4i+1)
                ulonglong2 qb = xq[2 * i + 1];   // k-pair (c0+4i+2, c0+4i+3)
                asm("fma.rn.f32x2 %0, %1, %2, %0;" : "+l"(acc[rp]) : "l"(qa.x), "l"(wp[4 * i + 0]));
                asm("fma.rn.f32x2 %0, %1, %2, %0;" : "+l"(acc[rp]) : "l"(qa.y), "l"(wp[4 * i + 1]));
                asm("fma.rn.f32x2 %0, %1, %2, %0;" : "+l"(acc[rp]) : "l"(qb.x), "l"(wp[4 * i + 2]));
                asm("fma.rn.f32x2 %0, %1, %2, %0;" : "+l"(acc[rp]) : "l"(qb.y), "l"(wp[4 * i + 3]));
            }
        }
    }

    float b = bias ? bias[c] : 0.0f;
#pragma unroll
    for (int rp = 0; rp < 16; rp++) {
        float lo, hi;
        asm("mov.b64 {%0, %1}, %2;" : "=f"(lo), "=f"(hi) : "l"(acc[rp]));
        lo += b; hi += b;
        if (ACT) { lo = leaky(lo); hi = leaky(hi); }
        Y[(size_t)(row0 + 2 * rp + 0) * HID + c] = lo;
        Y[(size_t)(row0 + 2 * rp + 1) * HID + c] = hi;
    }
}

// ----------------------------------------------------------------------------
// GraphNorm + leaky + mean pool (float4). Block per graph, 256 threads
// = 8 node-groups x 32 float4-channels. Reads g_conv, writes Y and mout.
// ----------------------------------------------------------------------------
__global__ __launch_bounds__(256) void norm_kernel(
    float* __restrict__ Y,
    const float* __restrict__ alpha, const float* __restrict__ gamma,
    const float* __restrict__ beta, float* __restrict__ mout)
{
    __shared__ float4 s1[8][32], s2[8][32];
    __shared__ float4 sma[32], ssc[32], sbt[32];
    const int c4 = threadIdx.x & 31;
    const int q  = threadIdx.x >> 5;
    const int g  = blockIdx.x;
    const int nbeg = g * NPG + q * (NPG / 8);
    const float4* Xv = reinterpret_cast<const float4*>(g_conv);
    float4* Yv = reinterpret_cast<float4*>(Y);

    float4 s = {0, 0, 0, 0}, ss = {0, 0, 0, 0};
#pragma unroll 5
    for (int i = 0; i < NPG / 8; i++) {
        float4 v = Xv[(size_t)(nbeg + i) * 32 + c4];
        s.x += v.x; s.y += v.y; s.z += v.z; s.w += v.w;
        ss.x += v.x * v.x; ss.y += v.y * v.y; ss.z += v.z * v.z; ss.w += v.w * v.w;
    }
    s1[q][c4] = s; s2[q][c4] = ss;
    __syncthreads();
    if (q == 0) {
        float4 S = {0, 0, 0, 0}, SS = {0, 0, 0, 0};
#pragma unroll
        for (int j = 0; j < 8; j++) {
            S.x += s1[j][c4].x; S.y += s1[j][c4].y; S.z += s1[j][c4].z; S.w += s1[j][c4].w;
            SS.x += s2[j][c4].x; SS.y += s2[j][c4].y; SS.z += s2[j][c4].z; SS.w += s2[j][c4].w;
        }
        float4 av = reinterpret_cast<const float4*>(alpha)[c4];
        float4 gv = reinterpret_cast<const float4*>(gamma)[c4];
        float4 bv = reinterpret_cast<const float4*>(beta)[c4];
        const float inv = 1.0f / NPG;
        float4 mean = {S.x * inv, S.y * inv, S.z * inv, S.w * inv};
        // E[(x - a*mean)^2] = E[x^2] - mean^2 * a * (2 - a)
        float4 var;
        var.x = SS.x * inv - mean.x * mean.x * av.x * (2.0f - av.x);
        var.y = SS.y * inv - mean.y * mean.y * av.y * (2.0f - av.y);
        var.z = SS.z * inv - mean.z * mean.z * av.z * (2.0f - av.z);
        var.w = SS.w * inv - mean.w * mean.w * av.w * (2.0f - av.w);
        float4 ma = {av.x * mean.x, av.y * mean.y, av.z * mean.z, av.w * mean.w};
        float4 sc;
        sc.x = gv.x * rsqrtf(var.x + 1e-5f);
        sc.y = gv.y * rsqrtf(var.y + 1e-5f);
        sc.z = gv.z * rsqrtf(var.z + 1e-5f);
        sc.w = gv.w * rsqrtf(var.w + 1e-5f);
        sma[c4] = ma; ssc[c4] = sc; sbt[c4] = bv;
    }
    __syncthreads();
    float4 ma = sma[c4], sc = ssc[c4], bt = sbt[c4];
    float4 ms = {0, 0, 0, 0};
#pragma unroll 5
    for (int i = 0; i < NPG / 8; i++) {
        float4 v = Xv[(size_t)(nbeg + i) * 32 + c4];
        float4 y;
        y.x = leaky(sc.x * (v.x - ma.x) + bt.x);
        y.y = leaky(sc.y * (v.y - ma.y) + bt.y);
        y.z = leaky(sc.z * (v.z - ma.z) + bt.z);
        y.w = leaky(sc.w * (v.w - ma.w) + bt.w);
        Yv[(size_t)(nbeg + i) * 32 + c4] = y;
        ms.x += y.x; ms.y += y.y; ms.z += y.z; ms.w += y.w;
    }
    s1[q][c4] = ms;
    __syncthreads();
    if (q == 0) {
        float4 S = {0, 0, 0, 0};
#pragma unroll
        for (int j = 0; j < 8; j++) {
            S.x += s1[j][c4].x; S.y += s1[j][c4].y; S.z += s1[j][c4].z; S.w += s1[j][c4].w;
        }
        const float inv = 1.0f / NPG;
        float4 o = {S.x * inv, S.y * inv, S.z * inv, S.w * inv};
        reinterpret_cast<float4*>(mout)[g * 32 + c4] = o;
    }
}

// mean-pool g_phi over graph -> g_pool (float4)
__global__ __launch_bounds__(256) void pool_kernel() {
    __shared__ float4 s1[8][32];
    const int c4 = threadIdx.x & 31;
    const int q  = threadIdx.x >> 5;
    const int g  = blockIdx.x;
    const int nbeg = g * NPG + q * (NPG / 8);
    const float4* Xv = reinterpret_cast<const float4*>(g_phi);
    float4 s = {0, 0, 0, 0};
#pragma unroll 5
    for (int i = 0; i < NPG / 8; i++) {
        float4 v = Xv[(size_t)(nbeg + i) * 32 + c4];
        s.x += v.x; s.y += v.y; s.z += v.z; s.w += v.w;
    }
    s1[q][c4] = s;
    __syncthreads();
    if (q == 0) {
        float4 S = {0, 0, 0, 0};
#pragma unroll
        for (int j = 0; j < 8; j++) {
            S.x += s1[j][c4].x; S.y += s1[j][c4].y; S.z += s1[j][c4].z; S.w += s1[j][c4].w;
        }
        const float inv = 1.0f / NPG;
        float4 o = {S.x * inv, S.y * inv, S.z * inv, S.w * inv};
        reinterpret_cast<float4*>(g_pool)[g * 32 + c4] = o;
    }
}

// rho: r[g][j] = leaky( pool[g] . w2[:,j] + b2[j] )   (w2: [128,64] row-major)
__global__ __launch_bounds__(64) void rho_kernel(
    const float* __restrict__ w2, const float* __restrict__ b2, float* __restrict__ r)
{
    __shared__ float p[HID];
    const int g = blockIdx.x, j = threadIdx.x;
    for (int k = j; k < HID; k += 64) p[k] = g_pool[g * HID + k];
    __syncthreads();
    float acc = b2[j];
#pragma unroll 8
    for (int k = 0; k < HID; k++) acc += p[k] * w2[k * RD + j];
    r[g * RD + j] = leaky(acc);
}

// final assemble: out = leaky(concat(r1, m1, r2, m2))  -> [100, 384]
__global__ void final_kernel(float* __restrict__ out) {
    int i = blockIdx.x * blockDim.x + threadIdx.x;
    if (i >= N_GRAPHS * 384) return;
    int g = i / 384, k = i - g * 384;
    float v;
    if (k < 64)        v = g_r1[g * RD + k];
    else if (k < 192)  v = g_m1[g * HID + (k - 64)];
    else if (k < 256)  v = g_r2[g * RD + (k - 192)];
    else               v = g_m2[g * HID + (k - 256)];
    out[i] = leaky(v);
}

// ----------------------------------------------------------------------------
// Launch
// ----------------------------------------------------------------------------
extern "C" void kernel_launch(void* const* d_in, const int* in_sizes, int n_in,
                              void* d_out, int out_size)
{
    const float* node_feats = (const float*)d_in[0];
    const float* edge_w     = (const float*)d_in[1];
    const float* W1         = (const float*)d_in[2];
    const float* W2         = (const float*)d_in[3];
    const float* gn1a = (const float*)d_in[4];
    const float* gn1g = (const float*)d_in[5];
    const float* gn1b = (const float*)d_in[6];
    const float* gn2a = (const float*)d_in[7];
    const float* gn2g = (const float*)d_in[8];
    const float* gn2b = (const float*)d_in[9];
    const float* r1w1 = (const float*)d_in[10];
    const float* r1b1 = (const float*)d_in[11];
    const float* r1w2 = (const float*)d_in[12];
    const float* r1b2 = (const float*)d_in[13];
    const float* r2w1 = (const float*)d_in[14];
    const float* r2b1 = (const float*)d_in[15];
    const float* r2w2 = (const float*)d_in[16];
    const float* r2b2 = (const float*)d_in[17];
    const int* src = (const int*)d_in[18];
    const int* dst = (const int*)d_in[19];

    float *pAgg, *pConv, *pH1, *pH2, *pPhi, *pM1, *pM2, *pR1, *pR2;
    cudaGetSymbolAddress((void**)&pAgg,  g_agg);
    cudaGetSymbolAddress((void**)&pConv, g_conv);
    cudaGetSymbolAddress((void**)&pH1,   g_h1);
    cudaGetSymbolAddress((void**)&pH2,   g_h2);
    cudaGetSymbolAddress((void**)&pPhi,  g_phi);
    cudaGetSymbolAddress((void**)&pM1,   g_m1);
    cudaGetSymbolAddress((void**)&pM2,   g_m2);
    cudaGetSymbolAddress((void**)&pR1,   g_r1);
    cudaGetSymbolAddress((void**)&pR2,   g_r2);

    // (0) prep: degrees + iso/isi + CSR (iso folded into edge weight)
    prep_kernel<<<N_GRAPHS, 512>>>(src, dst, edge_w);

    // layer 1: aggregate-then-GEMM (linearity: agg(X)@W == agg(X@W))
    gather_kernel<64><<<N_NODES / 8, 256>>>(node_feats, pAgg);          // (1)
    gemm_kernel<64, false><<<N_NODES / 32, 128>>>(pAgg, W1, nullptr, pConv); // (2)
    norm_kernel<<<N_GRAPHS, 256>>>(pH1, gn1a, gn1g, gn1b, pM1);          // (3)

    // layer 2
    gather_kernel<128><<<N_NODES / 8, 256>>>(pH1, pAgg);                 // (4)
    gemm_kernel<128, false><<<N_NODES / 32, 128>>>(pAgg, W2, nullptr, pConv); // (5) <- ncu -s 5
    norm_kernel<<<N_GRAPHS, 256>>>(pH2, gn2a, gn2g, gn2b, pM2);          // (6)

    // readouts
    gemm_kernel<128, true><<<N_NODES / 32, 128>>>(pH1, r1w1, r1b1, pPhi);
    pool_kernel<<<N_GRAPHS, 256>>>();
    rho_kernel<<<N_GRAPHS, 64>>>(r1w2, r1b2, pR1);

    gemm_kernel<128, true><<<N_NODES / 32, 128>>>(pH2, r2w1, r2b1, pPhi);
    pool_kernel<<<N_GRAPHS, 256>>>();
    rho_kernel<<<N_GRAPHS, 64>>>(r2w2, r2b2, pR2);

    final_kernel<<<(N_GRAPHS * 384 + 255) / 256, 256>>>((float*)d_out);
}